// round 10
// baseline (speedup 1.0000x reference)
#include <cuda_runtime.h>
#include <math.h>

// Problem shape (fixed by the dataset)
#define BB 16
#define NN 8192
#define KK 128
#define MM (NN + KK)          // 8320
#define RPB 64                // rois per k_iou block (split-K x4, 256 thr)
#define NCHUNK 130            // MM / RPB
#define WRPB 128              // rois per k_write block
#define NWBLK 65              // MM / WRPB
#define FG_THRESH 0.5f

// Scratch (no allocations allowed -> __device__ globals)
__device__ float g_maxov[BB * MM];
__device__ int   g_garg [BB * MM];
__device__ int   g_blkcnt[BB * NCHUNK];

// Guard band: 1 +- ~2^-19. Clear-greater => rounded quotients strictly
// ordered; in-band (incl. exact ties) => exact reference loop resolves.
#define EPS_HI 1.000002f
#define EPS_LO 0.999998f

// ---------------------------------------------------------------------------
// Kernel 1: per-roi max IoU + argmax. Split-K x4 (64 rois/block, 4 threads
// per roi, 32 gt each) + two interleaved accumulators per thread to cut the
// loop-carried compare chain. Cross-multiplied comparisons with guard band;
// any ambiguous compare -> flag -> bit-exact reference loop (with __fdiv_rn).
// Epilogue: per-block fg count -> g_blkcnt.
// ---------------------------------------------------------------------------
__global__ __launch_bounds__(256)
void k_iou(const float* __restrict__ rois, const float* __restrict__ gt)
{
    __shared__ float4 s_g [KK];
    __shared__ float  s_ga[KK];
    __shared__ float  s_bi [3][RPB];
    __shared__ float  s_bd [3][RPB];
    __shared__ int    s_bkf[3][RPB];
    __shared__ int    s_cnt[2];

    const int b = blockIdx.y;
    const int t = threadIdx.x;
    const int r = t & (RPB - 1);      // roi slot
    const int q = t >> 6;             // k-quarter 0..3 (warp-uniform)

    if (t < KK) {
        const float* g = gt + ((size_t)b * KK + t) * 5;
        float gx1 = g[0], gy1 = g[1], gx2 = g[2], gy2 = g[3];
        float gw = __fadd_rn(__fsub_rn(gx2, gx1), 1.0f);
        float gh = __fadd_rn(__fsub_rn(gy2, gy1), 1.0f);
        bool  z  = (gw == 1.0f && gh == 1.0f);
        s_g[t]  = z ? make_float4(3.0e38f, 3.0e38f, -3.0e38f, -3.0e38f)
                    : make_float4(gx1, gy1, gx2, gy2);
        s_ga[t] = __fmul_rn(gw, gh);
    }
    __syncthreads();

    const int m = blockIdx.x * RPB + r;    // < MM (130*64 == MM)

    float x1, y1, x2, y2;
    if (m < NN) {
        const float* p = rois + ((size_t)b * NN + m) * 5;
        x1 = p[1]; y1 = p[2]; x2 = p[3]; y2 = p[4];
    } else {
        const float* p = gt + ((size_t)b * KK + (m - NN)) * 5;
        x1 = p[0]; y1 = p[1]; x2 = p[2]; y2 = p[3];
    }

    float aw    = __fadd_rn(__fsub_rn(x2, x1), 1.0f);
    float ah    = __fadd_rn(__fsub_rn(y2, y1), 1.0f);
    float areaA = __fmul_rn(aw, ah);

    float biA = 0.0f, bdA = 1.0f, biB = 0.0f, bdB = 1.0f;
    int   bkA = 0,    bkB = 0;
    bool  flag = false;
    const int kbase = q << 5;

#pragma unroll
    for (int j = 0; j < 16; j++) {
        {   // even slot -> accumulator A
            const int k = kbase + 2 * j;
            float4 g  = s_g[k];
            float ix1 = fmaxf(x1, g.x);
            float iy1 = fmaxf(y1, g.y);
            float ix2 = fminf(x2, g.z);
            float iy2 = fminf(y2, g.w);
            float iw  = fmaxf(__fadd_rn(__fsub_rn(ix2, ix1), 1.0f), 0.0f);
            float ih  = fmaxf(__fadd_rn(__fsub_rn(iy2, iy1), 1.0f), 0.0f);
            float inter = __fmul_rn(iw, ih);
            float denom = __fsub_rn(__fadd_rn(areaA, s_ga[k]), inter);
            float lhs = __fmul_rn(inter, bdA);
            float rhs = __fmul_rn(biA, denom);
            if (lhs > __fmul_rn(rhs, EPS_HI)) { biA = inter; bdA = denom; bkA = k; }
            else if (lhs > 0.0f && lhs >= __fmul_rn(rhs, EPS_LO)) flag = true;
        }
        {   // odd slot -> accumulator B (independent chain)
            const int k = kbase + 2 * j + 1;
            float4 g  = s_g[k];
            float ix1 = fmaxf(x1, g.x);
            float iy1 = fmaxf(y1, g.y);
            float ix2 = fminf(x2, g.z);
            float iy2 = fminf(y2, g.w);
            float iw  = fmaxf(__fadd_rn(__fsub_rn(ix2, ix1), 1.0f), 0.0f);
            float ih  = fmaxf(__fadd_rn(__fsub_rn(iy2, iy1), 1.0f), 0.0f);
            float inter = __fmul_rn(iw, ih);
            float denom = __fsub_rn(__fadd_rn(areaA, s_ga[k]), inter);
            float lhs = __fmul_rn(inter, bdB);
            float rhs = __fmul_rn(biB, denom);
            if (lhs > __fmul_rn(rhs, EPS_HI)) { biB = inter; bdB = denom; bkB = k; }
            else if (lhs > 0.0f && lhs >= __fmul_rn(rhs, EPS_LO)) flag = true;
        }
    }

    // merge B into A: switch only if clearly greater; nonzero tie -> flag
    {
        float lhs = __fmul_rn(biB, bdA);
        float rhs = __fmul_rn(biA, bdB);
        if (lhs > __fmul_rn(rhs, EPS_HI)) { biA = biB; bdA = bdB; bkA = bkB; }
        else if (lhs > 0.0f && lhs >= __fmul_rn(rhs, EPS_LO)) flag = true;
    }

    if (q > 0) {
        s_bi [q-1][r] = biA;
        s_bd [q-1][r] = bdA;
        s_bkf[q-1][r] = bkA | (flag ? 256 : 0);
    }
    __syncthreads();

    bool fgv = false;
    if (q == 0) {                       // warps 0-1: uniform, no divergence
        // merge quarters 1..3 (ascending k => current acc wins ties; ties flag)
#pragma unroll
        for (int p = 0; p < 3; p++) {
            float ci = s_bi[p][r], cd = s_bd[p][r];
            int   cf = s_bkf[p][r];
            flag = flag || (cf & 256);
            float lhs = __fmul_rn(ci, bdA);
            float rhs = __fmul_rn(biA, cd);
            if (lhs > __fmul_rn(rhs, EPS_HI)) { biA = ci; bdA = cd; bkA = cf & 255; }
            else if (lhs > 0.0f && lhs >= __fmul_rn(rhs, EPS_LO)) flag = true;
        }

        float best;
        int   bestk;
        if (flag) {
            // exact reference loop (rare): rounded quotients, strict >, first idx
            best = -1e30f; bestk = 0;
#pragma unroll 4
            for (int k = 0; k < KK; k++) {
                float4 g  = s_g[k];
                float ix1 = fmaxf(x1, g.x);
                float iy1 = fmaxf(y1, g.y);
                float ix2 = fminf(x2, g.z);
                float iy2 = fminf(y2, g.w);
                float iw  = fmaxf(__fadd_rn(__fsub_rn(ix2, ix1), 1.0f), 0.0f);
                float ih  = fmaxf(__fadd_rn(__fsub_rn(iy2, iy1), 1.0f), 0.0f);
                float inter = __fmul_rn(iw, ih);
                float denom = __fsub_rn(__fadd_rn(areaA, s_ga[k]), inter);
                float ov    = __fdiv_rn(inter, denom);
                if (ov > best) { best = ov; bestk = k; }
            }
        } else {
            best  = __fdiv_rn(biA, bdA);   // rounding is monotone
            bestk = bkA;
        }

        if (aw == 1.0f && ah == 1.0f) { best = -1.0f; bestk = 0; }  // an_zero
        g_maxov[b * MM + m] = best;
        g_garg [b * MM + m] = bestk;
        fgv = (best >= FG_THRESH);
    }

    unsigned bal = __ballot_sync(0xffffffffu, fgv);
    if ((t & 31) == 0 && t < 64) s_cnt[t >> 5] = __popc(bal);
    __syncthreads();
    if (t == 0)
        g_blkcnt[b * NCHUNK + blockIdx.x] = s_cnt[0] + s_cnt[1];
}

// ---------------------------------------------------------------------------
// Kernel 2: destination index inline (parallel scan over 130 chunk counts +
// in-block ballot) and scatter all five outputs.
// ---------------------------------------------------------------------------
__global__ __launch_bounds__(WRPB)
void k_write(const float* __restrict__ rois, const float* __restrict__ gt,
             float* __restrict__ out)
{
    __shared__ int s_c[NCHUNK];
    __shared__ int s_scan[WRPB];
    __shared__ int s_wsum[4];
    __shared__ int s_w[4];

    const int b    = blockIdx.y;
    const int blk  = blockIdx.x;
    const int t    = threadIdx.x;
    const int lane = t & 31;
    const int w    = t >> 5;

    const int m   = blk * WRPB + t;
    const int idx = b * MM + m;

    // issue data loads early (overlap with the scan below)
    const float best = g_maxov[idx];
    const int   ga   = g_garg[idx];
    const bool  fg   = (best >= FG_THRESH);

    float x1, y1, x2, y2;
    if (m < NN) {
        const float* r = rois + ((size_t)b * NN + m) * 5;
        x1 = r[1]; y1 = r[2]; x2 = r[3]; y2 = r[4];
    } else {
        const float* g = gt + ((size_t)b * KK + (m - NN)) * 5;
        x1 = g[0]; y1 = g[1]; x2 = g[2]; y2 = g[3];
    }
    const float* g = gt + ((size_t)b * KK + ga) * 5;
    const float gx1 = g[0], gy1 = g[1], gx2 = g[2], gy2 = g[3], cls = g[4];

    // stage chunk counts and parallel-scan the first 128
    for (int j = t; j < NCHUNK; j += WRPB) s_c[j] = g_blkcnt[b * NCHUNK + j];
    __syncthreads();
    {
        int x = s_c[t];
        for (int o = 1; o < 32; o <<= 1) {
            int y = __shfl_up_sync(0xffffffffu, x, o);
            if (lane >= o) x += y;
        }
        if (lane == 31) s_wsum[w] = x;
        __syncthreads();
        int off = 0;
        for (int i = 0; i < w; i++) off += s_wsum[i];
        s_scan[t] = x + off;
    }

    // in-block fg prefix via ballot
    unsigned bal = __ballot_sync(0xffffffffu, fg);
    if (lane == 0) s_w[w] = __popc(bal);
    __syncthreads();

    const int tot = s_scan[WRPB - 1] + s_c[128] + s_c[129];
    const int pre = (blk == 0) ? 0 : s_scan[2 * blk - 1];

    int lex = __popc(bal & ((1u << lane) - 1u));
    for (int i = 0; i < w; i++) lex += s_w[i];
    const int nfg_before = pre + lex;
    const int d = fg ? nfg_before : (tot + m - nfg_before);

    float*  o_rois = out;
    float*  o_lab  = out   + (size_t)BB * MM * 5;
    float4* o_tgt  = (float4*)(o_lab + (size_t)BB * MM);
    float4* o_in   = o_tgt + (size_t)BB * MM;
    float4* o_out  = o_in  + (size_t)BB * MM;

    const size_t dd = (size_t)b * MM + d;   // permuted position
    const size_t mm = (size_t)idx;          // original position

    o_rois[dd * 5 + 0] = (float)b;
    o_rois[dd * 5 + 1] = x1;
    o_rois[dd * 5 + 2] = y1;
    o_rois[dd * 5 + 3] = x2;
    o_rois[dd * 5 + 4] = y2;

    o_lab[dd] = fg ? cls : 0.0f;

    float t0 = 0.f, t1 = 0.f, t2 = 0.f, t3 = 0.f;
    if (fg) {
        float ew  = x2 - x1 + 1.0f;
        float eh  = y2 - y1 + 1.0f;
        float ecx = x1 + 0.5f * ew;
        float ecy = y1 + 0.5f * eh;
        float gw  = gx2 - gx1 + 1.0f;
        float gh  = gy2 - gy1 + 1.0f;
        float gcx = gx1 + 0.5f * gw;
        float gcy = gy1 + 0.5f * gh;
        t0 = ((gcx - ecx) / ew) / 0.1f;
        t1 = ((gcy - ecy) / eh) / 0.1f;
        t2 = logf(gw / ew) / 0.2f;
        t3 = logf(gh / eh) / 0.2f;
    }
    o_tgt[dd] = make_float4(t0, t1, t2, t3);

    float om = __fsub_rn(1.0f, best);
    float wf = fg ? __fmul_rn(om, om) : 0.0f;
    float wo = (wf > 0.0f) ? 1.0f : 0.0f;
    o_in [mm] = make_float4(wf, wf, wf, wf);
    o_out[mm] = make_float4(wo, wo, wo, wo);
}

// ---------------------------------------------------------------------------
extern "C" void kernel_launch(void* const* d_in, const int* in_sizes, int n_in,
                              void* d_out, int out_size)
{
    const float* rois = (const float*)d_in[0];   // (B,N,5)
    const float* gt   = (const float*)d_in[1];   // (B,K,5)
    float*       out  = (float*)d_out;

    dim3 grid_iou(NCHUNK, BB);                   // 130 x 16 = 2080 blocks
    k_iou  <<<grid_iou, 256>>>(rois, gt);
    dim3 grid_w(NWBLK, BB);                      // 65 x 16
    k_write<<<grid_w, WRPB>>>(rois, gt, out);
}